// round 7
// baseline (speedup 1.0000x reference)
#include <cuda_runtime.h>
#include <math.h>
#include <stdint.h>

// Problem constants
#define BB   2
#define NN   2048
#define DD   2048
#define HH   16
#define DHH  128
#define MTOT (BB*NN)
#define SCALE 0.08838834764831845f  // DH^-0.5

// ---------------- device scratch ----------------
__device__ float g_Q[(size_t)BB*HH*NN*DHH];
__device__ float g_K[(size_t)BB*HH*NN*DHH];
__device__ float g_V[(size_t)BB*HH*NN*DHH];
__device__ float g_O[(size_t)MTOT*DD];
__device__ float g_gate[(size_t)MTOT*HH];
__device__ float g_Xc[(size_t)MTOT*DD];
__device__ float g_Wqc[(size_t)DD*DD];   // RNA-rounded copies (native [k][n] layout)
__device__ float g_Wkc[(size_t)DD*DD];
__device__ float g_Wvc[(size_t)DD*DD];
__device__ float g_Woc[(size_t)DD*DD];

// ================= helpers =================
__device__ __forceinline__ float tf32r(float x) {
    uint32_t u;
    asm("cvt.rna.tf32.f32 %0, %1;" : "=r"(u) : "f"(x));
    return __uint_as_float(u);
}
__device__ __forceinline__ void cp16(uint32_t dst, const void* src) {
    asm volatile("cp.async.cg.shared.global [%0], [%1], 16;" :: "r"(dst), "l"(src));
}
__device__ __forceinline__ void cp_commit() { asm volatile("cp.async.commit_group;" ::: "memory"); }
template<int N> __device__ __forceinline__ void cp_wait() {
    asm volatile("cp.async.wait_group %0;" :: "n"(N) : "memory");
}
__device__ __forceinline__ uint32_t smem_u32(const void* p) {
    uint32_t a;
    asm("{ .reg .u64 t; cvta.to.shared.u64 t, %1; cvt.u32.u64 %0, t; }" : "=r"(a) : "l"(p));
    return a;
}
__device__ __forceinline__ void mma_tf32(float* c, const uint32_t* a, const uint32_t* b) {
    asm volatile("mma.sync.aligned.m16n8k8.row.col.f32.tf32.tf32.f32 "
                 "{%0,%1,%2,%3}, {%4,%5,%6,%7}, {%8,%9}, {%0,%1,%2,%3};"
                 : "+f"(c[0]), "+f"(c[1]), "+f"(c[2]), "+f"(c[3])
                 : "r"(a[0]), "r"(a[1]), "r"(a[2]), "r"(a[3]), "r"(b[0]), "r"(b[1]));
}

// ================= RNA-rounding copies =================
__global__ void round_copy_kernel(const float* __restrict__ src, float* __restrict__ dst)
{
    int i = blockIdx.x * blockDim.x + threadIdx.x;
    float4 v = *(const float4*)(src + (size_t)i * 4);
    v.x = tf32r(v.x); v.y = tf32r(v.y); v.z = tf32r(v.z); v.w = tf32r(v.w);
    *(float4*)(dst + (size_t)i * 4) = v;
}

// ================= fused QKV GEMM ===========================================
// {Q,K,V}[4096,2048] = A[4096,2048] x W{q,k,v}[2048(k),2048(n)]
// block 128(M) x 128(N), BK=32, 8 warps (2m x 4n), warp 64x32, 3 stages.
// ONE A-tile per chunk feeds all three weight tiles (A frags amortized 3x).
#define BM 128
#define BN 128
#define BKG 32
#define PADA 36                          // frag bank: 4g+tg (conflict-free)
#define PADB 136                         // frag bank: 8tg+g (conflict-free)
#define A_ST (BM * PADA)                 // 4608 floats
#define B_ST (BKG * PADB)                // 4352 floats
#define QKV_STG 3
#define OFF_A  0
#define OFF_BQ (QKV_STG * A_ST)
#define OFF_BK (OFF_BQ + QKV_STG * B_ST)
#define OFF_BV (OFF_BK + QKV_STG * B_ST)
#define QKV_SMEM ((OFF_BV + QKV_STG * B_ST) * 4)   // 211,968 B
#define NCH (DD / BKG)                   // 64

__device__ __forceinline__ void qkv_load(float* sm_, int s,
                                         const float* __restrict__ A,
                                         int row0, int col0, int k0, int tid)
{
    uint32_t sb = smem_u32(sm_);
    {   // A tile: [128 rows][32 k]
        int r = tid >> 1, h = tid & 1;
        uint32_t dst = sb + (uint32_t)(OFF_A + s * A_ST + r * PADA + h * 16) * 4;
        const float* src = A + (size_t)(row0 + r) * DD + k0 + h * 16;
#pragma unroll
        for (int j = 0; j < 4; j++) cp16(dst + j * 16, src + j * 4);
    }
    {   // B tiles: [32 k-rows][128 cols] for each of Wq/Wk/Wv
        int r = tid >> 3, c = (tid & 7) * 16;
        size_t goff = (size_t)(k0 + r) * DD + col0 + c;
        uint32_t soff = (uint32_t)(r * PADB + c) * 4;
        uint32_t dq = sb + (uint32_t)(OFF_BQ + s * B_ST) * 4 + soff;
        uint32_t dk = sb + (uint32_t)(OFF_BK + s * B_ST) * 4 + soff;
        uint32_t dv = sb + (uint32_t)(OFF_BV + s * B_ST) * 4 + soff;
        const float* sq = g_Wqc + goff;
        const float* sk = g_Wkc + goff;
        const float* sv = g_Wvc + goff;
#pragma unroll
        for (int j = 0; j < 4; j++) {
            cp16(dq + j * 16, sq + j * 4);
            cp16(dk + j * 16, sk + j * 4);
            cp16(dv + j * 16, sv + j * 4);
        }
    }
}

__global__ __launch_bounds__(256, 1)
void qkv_fused_kernel(const float* __restrict__ A)
{
    extern __shared__ float sm[];

    const int tid = threadIdx.x;
    const int wid = tid >> 5, lane = tid & 31;
    const int g = lane >> 2, tg = lane & 3;
    const int wm = wid & 1, wn = wid >> 1;         // 2m x 4n
    const int row0 = blockIdx.y * BM;
    const int col0 = blockIdx.x * BN;

    float c[3][4][4][4];
#pragma unroll
    for (int t = 0; t < 3; t++)
#pragma unroll
        for (int mf = 0; mf < 4; mf++)
#pragma unroll
            for (int nf = 0; nf < 4; nf++)
#pragma unroll
                for (int r = 0; r < 4; r++) c[t][mf][nf][r] = 0.f;

    qkv_load(sm, 0, A, row0, col0, 0, tid);
    cp_commit();
    qkv_load(sm, 1, A, row0, col0, BKG, tid);
    cp_commit();

    for (int i = 0; i < NCH; i++) {
        if (i + 2 < NCH) cp_wait<1>();
        else             cp_wait<0>();
        __syncthreads();
        if (i + 2 < NCH) {
            qkv_load(sm, (i + 2) % QKV_STG, A, row0, col0, (i + 2) * BKG, tid);
            cp_commit();
        }

        const int st = i % QKV_STG;
        const float* As = sm + OFF_A + st * A_ST;
        const float* Bq = sm + OFF_BQ + st * B_ST;
        const float* Bk = sm + OFF_BK + st * B_ST;
        const float* Bv = sm + OFF_BV + st * B_ST;

#pragma unroll
        for (int ks = 0; ks < 4; ks++) {
            int k0 = ks * 8;
            uint32_t af[4][4];
#pragma unroll
            for (int mf = 0; mf < 4; mf++) {
                int rb = wm * 64 + mf * 16 + g;
                af[mf][0] = __float_as_uint(As[(rb)     * PADA + k0 + tg]);
                af[mf][1] = __float_as_uint(As[(rb + 8) * PADA + k0 + tg]);
                af[mf][2] = __float_as_uint(As[(rb)     * PADA + k0 + tg + 4]);
                af[mf][3] = __float_as_uint(As[(rb + 8) * PADA + k0 + tg + 4]);
            }
            // Q
            {
                uint32_t bf[4][2];
#pragma unroll
                for (int nf = 0; nf < 4; nf++) {
                    int cb = wn * 32 + nf * 8 + g;
                    bf[nf][0] = __float_as_uint(Bq[(k0 + tg)     * PADB + cb]);
                    bf[nf][1] = __float_as_uint(Bq[(k0 + tg + 4) * PADB + cb]);
                }
#pragma unroll
                for (int mf = 0; mf < 4; mf++)
#pragma unroll
                    for (int nf = 0; nf < 4; nf++)
                        mma_tf32(c[0][mf][nf], af[mf], bf[nf]);
            }
            // K
            {
                uint32_t bf[4][2];
#pragma unroll
                for (int nf = 0; nf < 4; nf++) {
                    int cb = wn * 32 + nf * 8 + g;
                    bf[nf][0] = __float_as_uint(Bk[(k0 + tg)     * PADB + cb]);
                    bf[nf][1] = __float_as_uint(Bk[(k0 + tg + 4) * PADB + cb]);
                }
#pragma unroll
                for (int mf = 0; mf < 4; mf++)
#pragma unroll
                    for (int nf = 0; nf < 4; nf++)
                        mma_tf32(c[1][mf][nf], af[mf], bf[nf]);
            }
            // V
            {
                uint32_t bf[4][2];
#pragma unroll
                for (int nf = 0; nf < 4; nf++) {
                    int cb = wn * 32 + nf * 8 + g;
                    bf[nf][0] = __float_as_uint(Bv[(k0 + tg)     * PADB + cb]);
                    bf[nf][1] = __float_as_uint(Bv[(k0 + tg + 4) * PADB + cb]);
                }
#pragma unroll
                for (int mf = 0; mf < 4; mf++)
#pragma unroll
                    for (int nf = 0; nf < 4; nf++)
                        mma_tf32(c[2][mf][nf], af[mf], bf[nf]);
            }
        }
    }

    // epilogue: split-head store (N-tile == one head: h = blockIdx.x)
    const int h = blockIdx.x;
#pragma unroll
    for (int t = 0; t < 3; t++) {
        float* C = (t == 0) ? g_Q : (t == 1) ? g_K : g_V;
        bool rnd = (t == 2);
#pragma unroll
        for (int mf = 0; mf < 4; mf++) {
#pragma unroll
            for (int nf = 0; nf < 4; nf++) {
                int dh = wn * 32 + nf * 8 + tg * 2;
#pragma unroll
                for (int half = 0; half < 2; half++) {
                    int m = row0 + wm * 64 + mf * 16 + g + half * 8;
                    int b = m >> 11, n = m & (NN - 1);
                    float* dp = C + (((size_t)(b * HH + h) * NN + n) * DHH + dh);
                    float v0 = c[t][mf][nf][half * 2], v1 = c[t][mf][nf][half * 2 + 1];
                    if (rnd) { v0 = tf32r(v0); v1 = tf32r(v1); }
                    dp[0] = v0;
                    dp[1] = v1;
                }
            }
        }
    }
}

// ================= tf32 GEMM (R5 style) for the output projection ===========
#define OBN 256
#define OPADA 36
#define OPADB 264
#define OA_ST (BM * OPADA)
#define OB_ST (BKG * OPADB)
#define OSTAGES 3
#define OGEMM_SMEM (OSTAGES * (OA_ST + OB_ST) * 4)

__device__ __forceinline__ void o_load(float* sA, float* sB, int s,
                                       const float* __restrict__ A,
                                       const float* __restrict__ W,
                                       int row0, int col0, int k0, int tid)
{
    {
        int r = tid >> 1, h = tid & 1;
        uint32_t dst = smem_u32(sA) + (uint32_t)(s * OA_ST + r * OPADA + h * 16) * 4;
        const float* src = A + (size_t)(row0 + r) * DD + k0 + h * 16;
#pragma unroll
        for (int j = 0; j < 4; j++) cp16(dst + j * 16, src + j * 4);
    }
    {
        int r = tid >> 3, c = (tid & 7) * 32;
        uint32_t dst = smem_u32(sB) + (uint32_t)(s * OB_ST + r * OPADB + c) * 4;
        const float* src = W + (size_t)(k0 + r) * DD + col0 + c;
#pragma unroll
        for (int j = 0; j < 8; j++) cp16(dst + j * 16, src + j * 4);
    }
}

__global__ __launch_bounds__(256, 1)
void gemm_o_kernel(const float* __restrict__ A, float* __restrict__ C)
{
    extern __shared__ float sm[];
    float* sA = sm;
    float* sB = sm + OSTAGES * OA_ST;
    const float* W = g_Woc;

    const int tid = threadIdx.x;
    const int wid = tid >> 5, lane = tid & 31;
    const int g = lane >> 2, tg = lane & 3;
    const int wm = wid & 1, wn = wid >> 1;
    const int row0 = blockIdx.y * BM;
    const int col0 = blockIdx.x * OBN;

    float c[4][8][4];
#pragma unroll
    for (int mf = 0; mf < 4; mf++)
#pragma unroll
        for (int nf = 0; nf < 8; nf++)
#pragma unroll
            for (int r = 0; r < 4; r++) c[mf][nf][r] = 0.f;

    o_load(sA, sB, 0, A, W, row0, col0, 0, tid);
    cp_commit();
    o_load(sA, sB, 1, A, W, row0, col0, BKG, tid);
    cp_commit();

    for (int i = 0; i < NCH; i++) {
        if (i + 2 < NCH) cp_wait<1>();
        else             cp_wait<0>();
        __syncthreads();
        if (i + 2 < NCH) {
            o_load(sA, sB, (i + 2) % OSTAGES, A, W, row0, col0, (i + 2) * BKG, tid);
            cp_commit();
        }

        const float* As = sA + (i % OSTAGES) * OA_ST;
        const float* Bs = sB + (i % OSTAGES) * OB_ST;
#pragma unroll
        for (int ks = 0; ks < 4; ks++) {
            int k0 = ks * 8;
            uint32_t af[4][4], bf[8][2];
#pragma unroll
            for (int mf = 0; mf < 4; mf++) {
                int rb = wm * 64 + mf * 16 + g;
                af[mf][0] = __float_as_uint(As[(rb)     * OPADA + k0 + tg]);
                af[mf][1] = __float_as_uint(As[(rb + 8) * OPADA + k0 + tg]);
                af[mf][2] = __float_as_uint(As[(rb)     * OPADA + k0 + tg + 4]);
                af[mf][3] = __float_as_uint(As[(rb + 8) * OPADA + k0 + tg + 4]);
            }
#pragma unroll
            for (int nf = 0; nf < 8; nf++) {
                int cb = wn * 64 + nf * 8 + g;
                bf[nf][0] = __float_as_uint(Bs[(k0 + tg)     * OPADB + cb]);
                bf[nf][1] = __float_as_uint(Bs[(k0 + tg + 4) * OPADB + cb]);
            }
#pragma unroll
            for (int mf = 0; mf < 4; mf++)
#pragma unroll
                for (int nf = 0; nf < 8; nf++)
                    mma_tf32(c[mf][nf], af[mf], bf[nf]);
        }
    }

#pragma unroll
    for (int mf = 0; mf < 4; mf++) {
#pragma unroll
        for (int nf = 0; nf < 8; nf++) {
            int col = col0 + wn * 64 + nf * 8 + tg * 2;
#pragma unroll
            for (int half = 0; half < 2; half++) {
                int m = row0 + wm * 64 + mf * 16 + g + half * 8;
                float* dp = C + (size_t)m * DD + col;
                dp[0] = c[mf][nf][half * 2];
                dp[1] = c[mf][nf][half * 2 + 1];
            }
        }
    }
}

// ================= RoPE (scale folded into Q, outputs tf32-rounded) =========
__global__ void rope_kernel(const float* __restrict__ freqs)
{
    int idx = blockIdx.x * blockDim.x + threadIdx.x;
    const int total = BB * HH * NN * 64;
    if (idx >= total) return;
    int half = idx & 63;
    int n = (idx >> 6) & (NN - 1);
    int bh = idx >> 17;

    const float* f = freqs + (size_t)n * DHH;
    float c1 = cosf(f[half]),      s1 = sinf(f[half]);
    float c2 = cosf(f[half + 64]), s2 = sinf(f[half + 64]);

    size_t base = ((size_t)bh * NN + n) * DHH;
    float q1 = g_Q[base + half], q2 = g_Q[base + half + 64];
    g_Q[base + half]      = tf32r((q1 * c1 - q2 * s1) * SCALE);
    g_Q[base + half + 64] = tf32r((q2 * c2 + q1 * s2) * SCALE);
    float k1 = g_K[base + half], k2 = g_K[base + half + 64];
    g_K[base + half]      = tf32r(k1 * c1 - k2 * s1);
    g_K[base + half + 64] = tf32r(k2 * c2 + k1 * s2);
}

// ================= Gate =================
__global__ void gate_kernel(const float* __restrict__ x,
                            const float* __restrict__ Wg,
                            const float* __restrict__ bg)
{
    int gw = (blockIdx.x * blockDim.x + threadIdx.x) >> 5;
    int lane = threadIdx.x & 31;
    if (gw >= MTOT) return;

    const float* xr = x + (size_t)gw * DD;
    float acc[HH];
#pragma unroll
    for (int h = 0; h < HH; h++) acc[h] = 0.f;

    for (int k = lane; k < DD; k += 32) {
        float xv = xr[k];
        const float* w = Wg + (size_t)k * HH;
#pragma unroll
        for (int h = 0; h < HH; h++) acc[h] = fmaf(xv, w[h], acc[h]);
    }
#pragma unroll
    for (int h = 0; h < HH; h++) {
#pragma unroll
        for (int off = 16; off > 0; off >>= 1)
            acc[h] += __shfl_xor_sync(0xffffffffu, acc[h], off);
    }
    if (lane == 0) {
#pragma unroll
        for (int h = 0; h < HH; h++)
            g_gate[(size_t)gw * HH + h] = 1.f / (1.f + expf(-(acc[h] + bg[h])));
    }
}

// ================= Flash attention (tf32 mma.sync, unchanged) ===============
#define KSTR 132
#define PSTR 68
#define KV_F (64 * KSTR)
#define FL_KS0 0
#define FL_KS1 (FL_KS0 + KV_F)
#define FL_VS0 (FL_KS1 + KV_F)
#define FL_VS1 (FL_VS0 + KV_F)
#define FL_PS  (FL_VS1 + KV_F)
#define FLASH_SMEM ((FL_PS + 128 * PSTR) * 4)
#define NT (NN / 64)

__device__ __forceinline__ void fl_load_kv(uint32_t sb, int stage,
                                           const float* __restrict__ Kg,
                                           const float* __restrict__ Vg,
                                           int kt, int tid)
{
    int row = tid >> 2;
    int part = tid & 3;
    uint32_t ks = sb + (uint32_t)(FL_KS0 + stage * KV_F + row * KSTR + part * 32) * 4;
    uint32_t vs = sb + (uint32_t)(FL_VS0 + stage * KV_F + row * KSTR + part * 32) * 4;
    const float* kg = Kg + (size_t)(kt * 64 + row) * DHH + part * 32;
    const float* vg = Vg + (size_t)(kt * 64 + row) * DHH + part * 32;
#pragma unroll
    for (int j = 0; j < 8; j++) {
        cp16(ks + j * 16, kg + j * 4);
        cp16(vs + j * 16, vg + j * 4);
    }
}

__global__ __launch_bounds__(256, 1)
void flash_tc_kernel()
{
    extern __shared__ float sm[];
    uint32_t sb = smem_u32(sm);
    float* Ps = sm + FL_PS;

    const int tid = threadIdx.x;
    const int wid = tid >> 5, lane = tid & 31;
    const int g = lane >> 2, tg = lane & 3;
    const int m0 = wid * 16;
    const int qt0 = blockIdx.x * 128;
    const int bh = blockIdx.y;

    const float* Qg = g_Q + (size_t)bh * NN * DHH;
    const float* Kg = g_K + (size_t)bh * NN * DHH;
    const float* Vg = g_V + (size_t)bh * NN * DHH;

    uint32_t aq[16][4];
    {
        float* stg = sm + FL_KS0;
#pragma unroll
        for (int chunk = 0; chunk < 2; chunk++) {
            int row = tid >> 2, part = tid & 3;
            const float* qg = Qg + (size_t)(qt0 + chunk * 64 + row) * DHH + part * 32;
#pragma unroll
            for (int j = 0; j < 8; j++)
                *(float4*)&stg[row * KSTR + part * 32 + j * 4] = *(const float4*)(qg + j * 4);
            __syncthreads();
            if (m0 >= chunk * 64 && m0 < chunk * 64 + 64) {
                int lm = m0 - chunk * 64;
#pragma unroll
                for (int ks = 0; ks < 16; ks++) {
                    aq[ks][0] = __float_as_uint(stg[(lm + g)     * KSTR + ks * 8 + tg]);
                    aq[ks][1] = __float_as_uint(stg[(lm + g + 8) * KSTR + ks * 8 + tg]);
                    aq[ks][2] = __float_as_uint(stg[(lm + g)     * KSTR + ks * 8 + tg + 4]);
                    aq[ks][3] = __float_as_uint(stg[(lm + g + 8) * KSTR + ks * 8 + tg + 4]);
                }
            }
            __syncthreads();
        }
    }

    float o[16][4];
#pragma unroll
    for (int nf = 0; nf < 16; nf++)
#pragma unroll
        for (int r = 0; r < 4; r++) o[nf][r] = 0.f;
    float mA = -1e30f, mB = -1e30f, lA = 0.f, lB = 0.f;

    fl_load_kv(sb, 0, Kg, Vg, 0, tid);
    cp_commit();

    for (int kt = 0; kt < NT; kt++) {
        int st = kt & 1;
        cp_wait<0>();
        __syncthreads();
        if (kt + 1 < NT) {
            fl_load_kv(sb, st ^ 1, Kg, Vg, kt + 1, tid);
            cp_commit();
        }

        const float* Ks = sm + FL_KS0 + st * KV_F;
        const float* Vs = sm + FL_VS0 + st * KV_F;

        float s[8][4];
#pragma unroll
        for (int nf = 0; nf < 8; nf++)
#pragma unroll
            for (int r = 0; r < 4; r++) s[nf][r] = 0.f;

#pragma unroll
        for (int ks = 0; ks < 16; ks++) {
#pragma unroll
            for (int nf = 0; nf < 8; nf++) {
                uint32_t bf[2];
                bf[0] = __float_as_uint(Ks[(nf * 8 + g) * KSTR + ks * 8 + tg]);
                bf[1] = __float_as_uint(Ks[(nf * 8 + g) * KSTR + ks * 8 + tg + 4]);
                mma_tf32(s[nf], aq[ks], bf);
            }
        }

        float mxA = -1e30f, mxB = -1e30f;
#pragma unroll
        for (int nf = 0; nf < 8; nf++) {
            mxA = fmaxf(mxA, fmaxf(s[nf][0], s[nf][1]));
            mxB = fmaxf(mxB, fmaxf(s[nf][2], s[nf][3]));
        }
        mxA = fmaxf(mxA, __shfl_xor_sync(0xffffffffu, mxA, 1));
        mxA = fmaxf(mxA, __shfl_xor_sync(0xffffffffu, mxA, 2));
        mxB = fmaxf(mxB, __shfl_xor_sync(0xffffffffu, mxB, 1));
        mxB = fmaxf(mxB, __shfl_xor_sync(0xffffffffu, mxB, 2));
        float mnA = fmaxf(mA, mxA), mnB = fmaxf(mB, mxB);
        float alA = __expf(mA - mnA), alB = __expf(mB - mnB);
        mA = mnA; mB = mnB;

        float smA = 0.f, smB = 0.f;
#pragma unroll
        for (int nf = 0; nf < 8; nf++) {
            float p0 = __expf(s[nf][0] - mnA);
            float p1 = __expf(s[nf][1] - mnA);
            float p2 = __expf(s[nf][2] - mnB);
            float p3 = __expf(s[nf][3] - mnB);
            smA += p0 + p1; smB += p2 + p3;
            int cb = nf * 8 + tg * 2;
            Ps[(m0 + g)     * PSTR + cb]     = tf32r(p0);
            Ps[(m0 + g)     * PSTR + cb + 1] = tf32r(p1);
            Ps[(m0 + g + 8) * PSTR + cb]     = tf32r(p2);
            Ps[(m0 + g + 8) * PSTR + cb + 1] = tf32r(p3);
        }
        smA += __shfl_xor_sync(0xffffffffu, smA, 1);
        smA += __shfl_xor_sync(0xffffffffu, smA, 2);
        smB += __shfl_xor_sync(0xffffffffu, smB, 1);
        smB += __shfl_xor_sync(0xffffffffu, smB, 2);
        lA = lA * alA + smA;
        lB = lB * alB + smB;

#pragma unroll
        for (int nf = 0; nf < 16; nf++) {
            o[nf][0] *= alA; o[nf][1] *= alA;
            o[nf][2] *= alB; o[nf][3] *= alB;
        }
        __syncwarp();

        uint32_t ap[8][4];
#pragma unroll
        for (int ks = 0; ks < 8; ks++) {
            ap[ks][0] = __float_as_uint(Ps[(m0 + g)     * PSTR + ks * 8 + tg]);
            ap[ks][1] = __float_as_uint(Ps[(m0 + g + 8) * PSTR + ks * 8 + tg]);
            ap[ks][2] = __float_as_uint(Ps[(m0 + g)     * PSTR + ks * 8 + tg + 4]);
            ap[ks][3] = __float_as_uint(Ps[(m0 + g + 8) * PSTR + ks * 8 + tg + 4]);
        }
#pragma unroll
        for (int ks = 0; ks < 8; ks++) {
#pragma unroll
            for (int nf = 0; nf < 16; nf++) {
                uint32_t bf[2];
                bf[0] = __float_as_uint(Vs[(ks * 8 + tg)     * KSTR + nf * 8 + g]);
                bf[1] = __float_as_uint(Vs[(ks * 8 + tg + 4) * KSTR + nf * 8 + g]);
                mma_tf32(o[nf], ap[ks], bf);
            }
        }
        __syncwarp();
    }

    const int b = bh >> 4, h = bh & 15;
    int nAr = qt0 + m0 + g, nBr = nAr + 8;
    float gA = g_gate[((size_t)(b * NN + nAr)) * HH + h];
    float gB = g_gate[((size_t)(b * NN + nBr)) * HH + h];
    float scA = gA / lA, scB = gB / lB;
    float* dA = g_O + ((size_t)(b * NN + nAr) * DD + h * DHH);
    float* dB = g_O + ((size_t)(b * NN + nBr) * DD + h * DHH);
#pragma unroll
    for (int nf = 0; nf < 16; nf++) {
        int dh = nf * 8 + tg * 2;
        *(float2*)(dA + dh) = make_float2(tf32r(o[nf][0] * scA), tf32r(o[nf][1] * scA));
        *(float2*)(dB + dh) = make_float2(tf32r(o[nf][2] * scB), tf32r(o[nf][3] * scB));
    }
}

// =====================================================================
extern "C" void kernel_launch(void* const* d_in, const int* in_sizes, int n_in,
                              void* d_out, int out_size)
{
    const float* x    = (const float*)d_in[0];
    const float* rope = (const float*)d_in[1];
    const float* Wq   = (const float*)d_in[2];
    const float* Wk   = (const float*)d_in[3];
    const float* Wv   = (const float*)d_in[4];
    const float* Wg   = (const float*)d_in[5];
    const float* bg   = (const float*)d_in[6];
    const float* Wo   = (const float*)d_in[7];
    float* out = (float*)d_out;

    float *wqc, *wkc, *wvc, *woc, *xc, *go;
    cudaGetSymbolAddress((void**)&wqc, g_Wqc);
    cudaGetSymbolAddress((void**)&wkc, g_Wkc);
    cudaGetSymbolAddress((void**)&wvc, g_Wvc);
    cudaGetSymbolAddress((void**)&woc, g_Woc);
    cudaGetSymbolAddress((void**)&xc, g_Xc);
    cudaGetSymbolAddress((void**)&go, g_O);

    cudaFuncSetAttribute(flash_tc_kernel,
                         cudaFuncAttributeMaxDynamicSharedMemorySize, FLASH_SMEM);
    cudaFuncSetAttribute(qkv_fused_kernel,
                         cudaFuncAttributeMaxDynamicSharedMemorySize, QKV_SMEM);
    cudaFuncSetAttribute(gemm_o_kernel,
                         cudaFuncAttributeMaxDynamicSharedMemorySize, OGEMM_SMEM);

    // 0) RNA-round weights and x
    int nW = DD * DD / 4;
    round_copy_kernel<<<nW / 256, 256>>>(Wq, wqc);
    round_copy_kernel<<<nW / 256, 256>>>(Wk, wkc);
    round_copy_kernel<<<nW / 256, 256>>>(Wv, wvc);
    round_copy_kernel<<<nW / 256, 256>>>(Wo, woc);
    round_copy_kernel<<<(MTOT * DD / 4) / 256, 256>>>(x, xc);

    // 1) fused QKV projections (shared A-tile across Q/K/V)
    {
        dim3 gg(DD / BN, MTOT / BM);
        qkv_fused_kernel<<<gg, 256, QKV_SMEM>>>(xc);
    }

    // 2) RoPE
    {
        int total = BB * HH * NN * 64;
        rope_kernel<<<(total + 255) / 256, 256>>>(rope);
    }

    // 3) head gates
    gate_kernel<<<(MTOT * 32 + 255) / 256, 256>>>(x, Wg, bg);

    // 4) flash attention (tensor cores) + gating + head merge
    {
        dim3 fg(NN / 128, BB * HH);
        flash_tc_kernel<<<fg, 256, FLASH_SMEM>>>();
    }

    // 5) output projection
    {
        dim3 gg(DD / OBN, MTOT / BM);
        gemm_o_kernel<<<gg, 256, OGEMM_SMEM>>>(go, out);
    }
}

// round 8
// speedup vs baseline: 1.9243x; 1.9243x over previous
#include <cuda_runtime.h>
#include <cuda_fp16.h>
#include <math.h>
#include <stdint.h>

#define BB   2
#define NN   2048
#define DD   2048
#define HH   16
#define DHH  128
#define MTOT (BB*NN)
#define SCALE 0.08838834764831845f

// ---------------- device scratch ----------------
__device__ __half g_Xh [(size_t)MTOT*DD];
__device__ __half g_WqT[(size_t)DD*DD];       // [n][k] fp16
__device__ __half g_WkT[(size_t)DD*DD];
__device__ __half g_WvT[(size_t)DD*DD];
__device__ __half g_WoT[(size_t)DD*DD];
__device__ float  g_Qf [(size_t)BB*HH*NN*DHH]; // fp32 pre-rope
__device__ float  g_Kf [(size_t)BB*HH*NN*DHH];
__device__ __half g_Qh [(size_t)BB*HH*NN*DHH]; // fp16 post-rope (+scale)
__device__ __half g_Kh [(size_t)BB*HH*NN*DHH];
__device__ __half g_Vh [(size_t)BB*HH*NN*DHH];
__device__ __half g_Oh [(size_t)MTOT*DD];      // gated merged heads
__device__ float  g_gate[(size_t)MTOT*HH];

// ================= asm helpers =================
__device__ __forceinline__ uint32_t smem_u32(const void* p) {
    uint32_t a;
    asm("{ .reg .u64 t; cvta.to.shared.u64 t, %1; cvt.u32.u64 %0, t; }" : "=r"(a) : "l"(p));
    return a;
}
__device__ __forceinline__ void cp16(uint32_t dst, const void* src) {
    asm volatile("cp.async.cg.shared.global [%0], [%1], 16;" :: "r"(dst), "l"(src));
}
__device__ __forceinline__ void cp_commit() { asm volatile("cp.async.commit_group;" ::: "memory"); }
template<int N> __device__ __forceinline__ void cp_wait() {
    asm volatile("cp.async.wait_group %0;" :: "n"(N) : "memory");
}
__device__ __forceinline__ void ldsm4(uint32_t* r, uint32_t a) {
    asm volatile("ldmatrix.sync.aligned.m8n8.x4.shared.b16 {%0,%1,%2,%3}, [%4];"
                 : "=r"(r[0]), "=r"(r[1]), "=r"(r[2]), "=r"(r[3]) : "r"(a));
}
__device__ __forceinline__ void ldsm4t(uint32_t* r, uint32_t a) {
    asm volatile("ldmatrix.sync.aligned.m8n8.x4.trans.shared.b16 {%0,%1,%2,%3}, [%4];"
                 : "=r"(r[0]), "=r"(r[1]), "=r"(r[2]), "=r"(r[3]) : "r"(a));
}
__device__ __forceinline__ void mma_f16(float* c, const uint32_t* a, uint32_t b0, uint32_t b1) {
    asm volatile("mma.sync.aligned.m16n8k16.row.col.f32.f16.f16.f32 "
                 "{%0,%1,%2,%3}, {%4,%5,%6,%7}, {%8,%9}, {%0,%1,%2,%3};"
                 : "+f"(c[0]), "+f"(c[1]), "+f"(c[2]), "+f"(c[3])
                 : "r"(a[0]), "r"(a[1]), "r"(a[2]), "r"(a[3]), "r"(b0), "r"(b1));
}
__device__ __forceinline__ uint32_t packh2(float lo, float hi) {
    __half2 h = __floats2half2_rn(lo, hi);
    return *reinterpret_cast<uint32_t*>(&h);
}

// ================= conversions =================
__global__ void conv_x_kernel(const float* __restrict__ x)
{
    size_t i = (size_t)(blockIdx.x * blockDim.x + threadIdx.x) * 8;
    float4 v0 = *(const float4*)(x + i);
    float4 v1 = *(const float4*)(x + i + 4);
    uint4 o;
    o.x = packh2(v0.x, v0.y); o.y = packh2(v0.z, v0.w);
    o.z = packh2(v1.x, v1.y); o.w = packh2(v1.z, v1.w);
    *(uint4*)(g_Xh + i) = o;
}

// W fp32 [k][n] -> Wt fp16 [n][k]
__global__ __launch_bounds__(256)
void conv_wT_kernel(const float* __restrict__ W, __half* __restrict__ Wt)
{
    __shared__ float t[32][33];
    int x = blockIdx.x * 32 + threadIdx.x;
    int y0 = blockIdx.y * 32 + threadIdx.y;
#pragma unroll
    for (int j = 0; j < 32; j += 8)
        t[threadIdx.y + j][threadIdx.x] = W[(size_t)(y0 + j) * DD + x];
    __syncthreads();
    int xo = blockIdx.y * 32 + threadIdx.x;
    int yo = blockIdx.x * 32 + threadIdx.y;
#pragma unroll
    for (int j = 0; j < 32; j += 8)
        Wt[(size_t)(yo + j) * DD + xo] = __float2half_rn(t[threadIdx.x][threadIdx.y + j]);
}

// ================= fused QKV GEMM (fp16 mma + ldmatrix) =====================
// tile 128(M rows of x) x 128(N = one head) x 3 weights, BK=64, 2 stages.
#define PADH 72
#define A_STH (128 * PADH)
#define B_STH (128 * PADH)
#define QKV_SMEM ((2 * A_STH + 6 * B_STH) * 2)   // 147,456 B

__device__ __forceinline__ void qkv_load(uint32_t sb, int s, int row0, int col0,
                                         int k0, int tid)
{
    int r = tid >> 1, hh = (tid & 1) * 32;
    {
        uint32_t dst = sb + (uint32_t)(s * A_STH + r * PADH + hh) * 2;
        const __half* src = g_Xh + (size_t)(row0 + r) * DD + k0 + hh;
#pragma unroll
        for (int j = 0; j < 4; j++) cp16(dst + j * 16, src + j * 8);
    }
    const __half* Ws[3] = {g_WqT, g_WkT, g_WvT};
#pragma unroll
    for (int w = 0; w < 3; w++) {
        uint32_t dst = sb + (uint32_t)(2 * A_STH + (w * 2 + s) * B_STH + r * PADH + hh) * 2;
        const __half* src = Ws[w] + (size_t)(col0 + r) * DD + k0 + hh;
#pragma unroll
        for (int j = 0; j < 4; j++) cp16(dst + j * 16, src + j * 8);
    }
}

__global__ __launch_bounds__(256, 1)
void qkv_h_kernel()
{
    extern __shared__ char smraw[];
    uint32_t sb = smem_u32(smraw);
    const int tid = threadIdx.x;
    const int wid = tid >> 5, lane = tid & 31;
    const int g = lane >> 2, tg = lane & 3;
    const int wm = wid & 1, wn = wid >> 1;
    const int row0 = blockIdx.y * 128;
    const int col0 = blockIdx.x * 128;
    const int lr = lane & 7, lb3 = (lane >> 3) & 1, lb4 = lane >> 4;

    float c[3][4][4][4];
#pragma unroll
    for (int t = 0; t < 3; t++)
#pragma unroll
        for (int mf = 0; mf < 4; mf++)
#pragma unroll
            for (int nf = 0; nf < 4; nf++)
#pragma unroll
                for (int r = 0; r < 4; r++) c[t][mf][nf][r] = 0.f;

    qkv_load(sb, 0, row0, col0, 0, tid);
    cp_commit();

    for (int i = 0; i < 32; i++) {
        cp_wait<0>();
        __syncthreads();
        if (i + 1 < 32) {
            qkv_load(sb, (i + 1) & 1, row0, col0, (i + 1) * 64, tid);
            cp_commit();
        }
        int s = i & 1;
        uint32_t Ab = sb + (uint32_t)(s * A_STH) * 2;
#pragma unroll
        for (int kk = 0; kk < 4; kk++) {
            uint32_t af[4][4];
#pragma unroll
            for (int mf = 0; mf < 4; mf++)
                ldsm4(af[mf], Ab + (uint32_t)((wm * 64 + mf * 16 + lb3 * 8 + lr) * PADH
                                              + kk * 16 + lb4 * 8) * 2);
#pragma unroll
            for (int w = 0; w < 3; w++) {
                uint32_t Bb = sb + (uint32_t)(2 * A_STH + (w * 2 + s) * B_STH) * 2;
#pragma unroll
                for (int np = 0; np < 2; np++) {
                    uint32_t bf[4];
                    ldsm4(bf, Bb + (uint32_t)((wn * 32 + np * 16 + lb4 * 8 + lr) * PADH
                                              + kk * 16 + lb3 * 8) * 2);
#pragma unroll
                    for (int mf = 0; mf < 4; mf++) {
                        mma_f16(c[w][mf][np * 2],     af[mf], bf[0], bf[1]);
                        mma_f16(c[w][mf][np * 2 + 1], af[mf], bf[2], bf[3]);
                    }
                }
            }
        }
    }

    // epilogue: Q,K fp32 (rounded once later in rope); V fp16 direct
    const int h = blockIdx.x;
#pragma unroll
    for (int mf = 0; mf < 4; mf++) {
#pragma unroll
        for (int nf = 0; nf < 4; nf++) {
            int dh = wn * 32 + nf * 8 + tg * 2;
#pragma unroll
            for (int hf = 0; hf < 2; hf++) {
                int m = row0 + wm * 64 + mf * 16 + g + hf * 8;
                int b = m >> 11, n = m & (NN - 1);
                size_t off = ((size_t)(b * HH + h) * NN + n) * DHH + dh;
                *(float2*)(g_Qf + off) = make_float2(c[0][mf][nf][hf * 2], c[0][mf][nf][hf * 2 + 1]);
                *(float2*)(g_Kf + off) = make_float2(c[1][mf][nf][hf * 2], c[1][mf][nf][hf * 2 + 1]);
                *(uint32_t*)(g_Vh + off) = packh2(c[2][mf][nf][hf * 2], c[2][mf][nf][hf * 2 + 1]);
            }
        }
    }
}

// ================= output projection (fp16 mma) ==============================
#define OGEMM_SMEM ((2 * A_STH + 2 * B_STH) * 2)   // 73,728 B

__device__ __forceinline__ void o_load(uint32_t sb, int s, int row0, int col0,
                                       int k0, int tid)
{
    int r = tid >> 1, hh = (tid & 1) * 32;
    {
        uint32_t dst = sb + (uint32_t)(s * A_STH + r * PADH + hh) * 2;
        const __half* src = g_Oh + (size_t)(row0 + r) * DD + k0 + hh;
#pragma unroll
        for (int j = 0; j < 4; j++) cp16(dst + j * 16, src + j * 8);
    }
    {
        uint32_t dst = sb + (uint32_t)(2 * A_STH + s * B_STH + r * PADH + hh) * 2;
        const __half* src = g_WoT + (size_t)(col0 + r) * DD + k0 + hh;
#pragma unroll
        for (int j = 0; j < 4; j++) cp16(dst + j * 16, src + j * 8);
    }
}

__global__ __launch_bounds__(256, 1)
void gemm_oh_kernel(float* __restrict__ out)
{
    extern __shared__ char smraw[];
    uint32_t sb = smem_u32(smraw);
    const int tid = threadIdx.x;
    const int wid = tid >> 5, lane = tid & 31;
    const int g = lane >> 2, tg = lane & 3;
    const int wm = wid & 1, wn = wid >> 1;
    const int row0 = blockIdx.y * 128;
    const int col0 = blockIdx.x * 128;
    const int lr = lane & 7, lb3 = (lane >> 3) & 1, lb4 = lane >> 4;

    float c[4][4][4];
#pragma unroll
    for (int mf = 0; mf < 4; mf++)
#pragma unroll
        for (int nf = 0; nf < 4; nf++)
#pragma unroll
            for (int r = 0; r < 4; r++) c[mf][nf][r] = 0.f;

    o_load(sb, 0, row0, col0, 0, tid);
    cp_commit();

    for (int i = 0; i < 32; i++) {
        cp_wait<0>();
        __syncthreads();
        if (i + 1 < 32) {
            o_load(sb, (i + 1) & 1, row0, col0, (i + 1) * 64, tid);
            cp_commit();
        }
        int s = i & 1;
        uint32_t Ab = sb + (uint32_t)(s * A_STH) * 2;
        uint32_t Bb = sb + (uint32_t)(2 * A_STH + s * B_STH) * 2;
#pragma unroll
        for (int kk = 0; kk < 4; kk++) {
            uint32_t af[4][4];
#pragma unroll
            for (int mf = 0; mf < 4; mf++)
                ldsm4(af[mf], Ab + (uint32_t)((wm * 64 + mf * 16 + lb3 * 8 + lr) * PADH
                                              + kk * 16 + lb4 * 8) * 2);
#pragma unroll
            for (int np = 0; np < 2; np++) {
                uint32_t bf[4];
                ldsm4(bf, Bb + (uint32_t)((wn * 32 + np * 16 + lb4 * 8 + lr) * PADH
                                          + kk * 16 + lb3 * 8) * 2);
#pragma unroll
                for (int mf = 0; mf < 4; mf++) {
                    mma_f16(c[mf][np * 2],     af[mf], bf[0], bf[1]);
                    mma_f16(c[mf][np * 2 + 1], af[mf], bf[2], bf[3]);
                }
            }
        }
    }

#pragma unroll
    for (int mf = 0; mf < 4; mf++) {
#pragma unroll
        for (int nf = 0; nf < 4; nf++) {
            int col = col0 + wn * 32 + nf * 8 + tg * 2;
#pragma unroll
            for (int hf = 0; hf < 2; hf++) {
                int m = row0 + wm * 64 + mf * 16 + g + hf * 8;
                *(float2*)(out + (size_t)m * DD + col) =
                    make_float2(c[mf][nf][hf * 2], c[mf][nf][hf * 2 + 1]);
            }
        }
    }
}

// ================= RoPE: fp32 in -> fp16 out (scale folded into Q) ==========
__global__ void rope_h_kernel(const float* __restrict__ freqs)
{
    int idx = blockIdx.x * blockDim.x + threadIdx.x;
    const int total = BB * HH * NN * 64;
    if (idx >= total) return;
    int half = idx & 63;
    int n = (idx >> 6) & (NN - 1);
    int bh = idx >> 17;

    const float* f = freqs + (size_t)n * DHH;
    float c1 = cosf(f[half]),      s1 = sinf(f[half]);
    float c2 = cosf(f[half + 64]), s2 = sinf(f[half + 64]);

    size_t base = ((size_t)bh * NN + n) * DHH;
    float q1 = g_Qf[base + half], q2 = g_Qf[base + half + 64];
    g_Qh[base + half]      = __float2half_rn((q1 * c1 - q2 * s1) * SCALE);
    g_Qh[base + half + 64] = __float2half_rn((q2 * c2 + q1 * s2) * SCALE);
    float k1 = g_Kf[base + half], k2 = g_Kf[base + half + 64];
    g_Kh[base + half]      = __float2half_rn(k1 * c1 - k2 * s1);
    g_Kh[base + half + 64] = __float2half_rn(k2 * c2 + k1 * s2);
}

// ================= Gate =================
__global__ void gate_kernel(const float* __restrict__ x,
                            const float* __restrict__ Wg,
                            const float* __restrict__ bg)
{
    int gw = (blockIdx.x * blockDim.x + threadIdx.x) >> 5;
    int lane = threadIdx.x & 31;
    if (gw >= MTOT) return;

    const float* xr = x + (size_t)gw * DD;
    float acc[HH];
#pragma unroll
    for (int h = 0; h < HH; h++) acc[h] = 0.f;
    for (int k = lane; k < DD; k += 32) {
        float xv = xr[k];
        const float* w = Wg + (size_t)k * HH;
#pragma unroll
        for (int h = 0; h < HH; h++) acc[h] = fmaf(xv, w[h], acc[h]);
    }
#pragma unroll
    for (int h = 0; h < HH; h++) {
#pragma unroll
        for (int off = 16; off > 0; off >>= 1)
            acc[h] += __shfl_xor_sync(0xffffffffu, acc[h], off);
    }
    if (lane == 0) {
#pragma unroll
        for (int h = 0; h < HH; h++)
            g_gate[(size_t)gw * HH + h] = 1.f / (1.f + expf(-(acc[h] + bg[h])));
    }
}

// ================= Flash attention (fp16 mma, register-resident P) ==========
#define FSTR 136
#define FKV (64 * FSTR)
#define FLASH_SMEM (4 * FKV * 2)   // 69,632 B (Q staging reuses K region)
#define NT (NN / 64)

__device__ __forceinline__ void fl_load_kv(uint32_t sb, int st,
                                           const __half* __restrict__ Kg,
                                           const __half* __restrict__ Vg,
                                           int kt, int tid)
{
    int row = tid >> 2, part = (tid & 3) * 32;
    uint32_t ks = sb + (uint32_t)(st * FKV + row * FSTR + part) * 2;
    uint32_t vs = sb + (uint32_t)((2 + st) * FKV + row * FSTR + part) * 2;
    const __half* kg = Kg + (size_t)(kt * 64 + row) * DHH + part;
    const __half* vg = Vg + (size_t)(kt * 64 + row) * DHH + part;
#pragma unroll
    for (int j = 0; j < 4; j++) {
        cp16(ks + j * 16, kg + j * 8);
        cp16(vs + j * 16, vg + j * 8);
    }
}

__global__ __launch_bounds__(256, 1)
void flash_h_kernel()
{
    extern __shared__ char smraw[];
    uint32_t sb = smem_u32(smraw);
    __half* smh = (__half*)smraw;

    const int tid = threadIdx.x;
    const int wid = tid >> 5, lane = tid & 31;
    const int g = lane >> 2, tg = lane & 3;
    const int m0 = wid * 16;
    const int qt0 = blockIdx.x * 128;
    const int bh = blockIdx.y;
    const int lr = lane & 7, lb3 = (lane >> 3) & 1, lb4 = lane >> 4;

    const __half* Qg = g_Qh + (size_t)bh * NN * DHH;
    const __half* Kg = g_Kh + (size_t)bh * NN * DHH;
    const __half* Vg = g_Vh + (size_t)bh * NN * DHH;

    // stage Q tile (128 x 128 fp16) into K region, harvest frags, then free it
    uint32_t aq[8][4];
    {
        int row = tid >> 1, part = (tid & 1) * 64;
        const __half* qg = Qg + (size_t)(qt0 + row) * DHH + part;
#pragma unroll
        for (int j = 0; j < 8; j++)
            *(uint4*)(smh + row * FSTR + part + j * 8) = *(const uint4*)(qg + j * 8);
        __syncthreads();
#pragma unroll
        for (int kc = 0; kc < 8; kc++)
            ldsm4(aq[kc], sb + (uint32_t)((m0 + lb3 * 8 + lr) * FSTR + kc * 16 + lb4 * 8) * 2);
        __syncthreads();
    }

    float o[16][4];
#pragma unroll
    for (int nf = 0; nf < 16; nf++)
#pragma unroll
        for (int r = 0; r < 4; r++) o[nf][r] = 0.f;
    float mA = -1e30f, mB = -1e30f, lA = 0.f, lB = 0.f;

    fl_load_kv(sb, 0, Kg, Vg, 0, tid);
    cp_commit();

    for (int kt = 0; kt < NT; kt++) {
        int st = kt & 1;
        cp_wait<0>();
        __syncthreads();
        if (kt + 1 < NT) {
            fl_load_kv(sb, st ^ 1, Kg, Vg, kt + 1, tid);
            cp_commit();
        }
        uint32_t Kb = sb + (uint32_t)(st * FKV) * 2;
        uint32_t Vb = sb + (uint32_t)((2 + st) * FKV) * 2;

        // S = Q K^T
        float s[8][4];
#pragma unroll
        for (int nf = 0; nf < 8; nf++)
#pragma unroll
            for (int r = 0; r < 4; r++) s[nf][r] = 0.f;
#pragma unroll
        for (int kc = 0; kc < 8; kc++) {
#pragma unroll
            for (int np = 0; np < 4; np++) {
                uint32_t bf[4];
                ldsm4(bf, Kb + (uint32_t)((np * 16 + lb4 * 8 + lr) * FSTR
                                          + kc * 16 + lb3 * 8) * 2);
                mma_f16(s[np * 2],     aq[kc], bf[0], bf[1]);
                mma_f16(s[np * 2 + 1], aq[kc], bf[2], bf[3]);
            }
        }

        // online softmax (rows g, g+8; reduce across tg quads)
        float mxA = -1e30f, mxB = -1e30f;
#pragma unroll
        for (int nf = 0; nf < 8; nf++) {
            mxA = fmaxf(mxA, fmaxf(s[nf][0], s[nf][1]));
            mxB = fmaxf(mxB, fmaxf(s[nf][2], s[nf][3]));
        }
        mxA = fmaxf(mxA, __shfl_xor_sync(0xffffffffu, mxA, 1));
        mxA = fmaxf(mxA, __shfl_xor_sync(0xffffffffu, mxA, 2));
        mxB = fmaxf(mxB, __shfl_xor_sync(0xffffffffu, mxB, 1));
        mxB = fmaxf(mxB, __shfl_xor_sync(0xffffffffu, mxB, 2));
        float mnA = fmaxf(mA, mxA), mnB = fmaxf(mB, mxB);
        float alA = __expf(mA - mnA), alB = __expf(mB - mnB);
        mA = mnA; mB = mnB;

        float smA = 0.f, smB = 0.f;
#pragma unroll
        for (int nf = 0; nf < 8; nf++) {
            s[nf][0] = __expf(s[nf][0] - mnA);
            s[nf][1] = __expf(s[nf][1] - mnA);
            s[nf][2] = __expf(s[nf][2] - mnB);
            s[nf][3] = __expf(s[nf][3] - mnB);
            smA += s[nf][0] + s[nf][1];
            smB += s[nf][2] + s[nf][3];
        }
        smA += __shfl_xor_sync(0xffffffffu, smA, 1);
        smA += __shfl_xor_sync(0xffffffffu, smA, 2);
        smB += __shfl_xor_sync(0xffffffffu, smB, 1);
        smB += __shfl_xor_sync(0xffffffffu, smB, 2);
        lA = lA * alA + smA;
        lB = lB * alB + smB;

#pragma unroll
        for (int nf = 0; nf < 16; nf++) {
            o[nf][0] *= alA; o[nf][1] *= alA;
            o[nf][2] *= alB; o[nf][3] *= alB;
        }

        // pack P into A-fragments (register pass, no smem)
        uint32_t ap[4][4];
#pragma unroll
        for (int j = 0; j < 4; j++) {
            ap[j][0] = packh2(s[2 * j][0],     s[2 * j][1]);
            ap[j][1] = packh2(s[2 * j][2],     s[2 * j][3]);
            ap[j][2] = packh2(s[2 * j + 1][0], s[2 * j + 1][1]);
            ap[j][3] = packh2(s[2 * j + 1][2], s[2 * j + 1][3]);
        }

        // O += P V  (V frags via ldmatrix.trans)
#pragma unroll
        for (int j = 0; j < 4; j++) {
#pragma unroll
            for (int nph = 0; nph < 8; nph++) {
                uint32_t bf[4];
                ldsm4t(bf, Vb + (uint32_t)((j * 16 + lb3 * 8 + lr) * FSTR
                                           + nph * 16 + lb4 * 8) * 2);
                mma_f16(o[nph * 2],     ap[j], bf[0], bf[1]);
                mma_f16(o[nph * 2 + 1], ap[j], bf[2], bf[3]);
            }
        }
    }

    // epilogue: normalize, gate, merge heads -> fp16 g_Oh
    const int b = bh >> 4, h = bh & 15;
    int nAr = qt0 + m0 + g, nBr = nAr + 8;
    float gA = g_gate[((size_t)(b * NN + nAr)) * HH + h];
    float gB = g_gate[((size_t)(b * NN + nBr)) * HH + h];
    float scA = gA / lA, scB = gB / lB;
    __half* dA = g_Oh + ((size_t)(b * NN + nAr) * DD + h * DHH);
    __half* dB = g_Oh + ((size_t)(b * NN + nBr) * DD + h * DHH);
#pragma unroll
    for (int nf = 0; nf < 16; nf++) {
        int dh = nf * 8 + tg * 2;
        *(uint32_t*)(dA + dh) = packh2(o[nf][0] * scA, o[nf][1] * scA);
        *(uint32_t*)(dB + dh) = packh2(o[nf][2] * scB, o[nf][3] * scB);
    }
}

// =====================================================================
extern "C" void kernel_launch(void* const* d_in, const int* in_sizes, int n_in,
                              void* d_out, int out_size)
{
    const float* x    = (const float*)d_in[0];
    const float* rope = (const float*)d_in[1];
    const float* Wq   = (const float*)d_in[2];
    const float* Wk   = (const float*)d_in[3];
    const float* Wv   = (const float*)d_in[4];
    const float* Wg   = (const float*)d_in[5];
    const float* bg   = (const float*)d_in[6];
    const float* Wo   = (const float*)d_in[7];
    float* out = (float*)d_out;

    __half *wqT, *wkT, *wvT, *woT;
    cudaGetSymbolAddress((void**)&wqT, g_WqT);
    cudaGetSymbolAddress((void**)&wkT, g_WkT);
    cudaGetSymbolAddress((void**)&wvT, g_WvT);
    cudaGetSymbolAddress((void**)&woT, g_WoT);

    cudaFuncSetAttribute(qkv_h_kernel,
                         cudaFuncAttributeMaxDynamicSharedMemorySize, QKV_SMEM);
    cudaFuncSetAttribute(gemm_oh_kernel,
                         cudaFuncAttributeMaxDynamicSharedMemorySize, OGEMM_SMEM);
    cudaFuncSetAttribute(flash_h_kernel,
                         cudaFuncAttributeMaxDynamicSharedMemorySize, FLASH_SMEM);

    // 0) conversions
    conv_x_kernel<<<(MTOT * DD / 8) / 256, 256>>>(x);
    dim3 tg(DD / 32, DD / 32), tb(32, 8);
    conv_wT_kernel<<<tg, tb>>>(Wq, wqT);
    conv_wT_kernel<<<tg, tb>>>(Wk, wkT);
    conv_wT_kernel<<<tg, tb>>>(Wv, wvT);
    conv_wT_kernel<<<tg, tb>>>(Wo, woT);

    // 1) fused QKV projections (launch index 5 -> ncu profile slot)
    {
        dim3 gg(DD / 128, MTOT / 128);
        qkv_h_kernel<<<gg, 256, QKV_SMEM>>>();
    }

    // 2) RoPE fp32->fp16
    {
        int total = BB * HH * NN * 64;
        rope_h_kernel<<<(total + 255) / 256, 256>>>(rope);
    }

    // 3) head gates
    gate_kernel<<<(MTOT * 32 + 255) / 256, 256>>>(x, Wg, bg);

    // 4) flash attention (fp16 tensor cores, register P)
    {
        dim3 fg(NN / 128, BB * HH);
        flash_h_kernel<<<fg, 256, FLASH_SMEM>>>();
    }

    // 5) output projection
    {
        dim3 gg(DD / 128, MTOT / 128);
        gemm_oh_kernel<<<gg, 256, OGEMM_SMEM>>>(out);
    }
}